// round 3
// baseline (speedup 1.0000x reference)
#include <cuda_runtime.h>

// Potts energy: out[b] = sum_{i<=j} W[i,j] * [(1-v_bi)(1-v_bj) + v_bi*v_bj]
// Per column j:  contrib = cs_j*(1-v_bj) + s1*(2*v_bj-1),
//                s1 = sum_i Wmask[i,j]*v_bi,  cs_j = sum_i Wmask[i,j]
// => masked 128x1024x1024 MAC, tiled 64x64 over upper triangle, f32x2 packed.

#define Bb      128
#define Nn      1024
#define T       64
#define NT      16
#define NTILES  136
#define WTS     68     // Wt row stride in floats (272B, 16B aligned)
#define VI2S    130    // Vi2 row stride in u64
#define VJS     129    // Vj row stride in floats
#define THREADS 512

__device__ float        g_accum[Bb];   // zero-initialized; reset every run
__device__ unsigned int g_count;       // zero-initialized; reset every run

__device__ __forceinline__ unsigned long long pack2(float lo, float hi) {
    unsigned long long r;
    asm("mov.b64 %0, {%1, %2};" : "=l"(r) : "f"(lo), "f"(hi));
    return r;
}
__device__ __forceinline__ void unpack2(unsigned long long v, float& lo, float& hi) {
    asm("mov.b64 {%0, %1}, %2;" : "=f"(lo), "=f"(hi) : "l"(v));
}
__device__ __forceinline__ unsigned long long fma2(unsigned long long a,
                                                   unsigned long long b,
                                                   unsigned long long c) {
    unsigned long long d;
    asm("fma.rn.f32x2 %0, %1, %2, %3;" : "=l"(d) : "l"(a), "l"(b), "l"(c));
    return d;
}

extern __shared__ unsigned long long smem_u64[];

__global__ void __launch_bounds__(THREADS, 1)
potts_fused_k(const float* __restrict__ V,   // [128,1024]
              const float* __restrict__ W,   // [1024,1024]
              float* __restrict__ out)       // [128]
{
    unsigned long long* Vi2 = smem_u64;                  // [32][VI2S] u64: (v[2p],v[2p+1]) per batch
    float* Wt  = (float*)(Vi2 + 32 * VI2S);              // [T][WTS]  Wt[j][i] transposed+masked
    float* Vj  = Wt + T * WTS;                           // [T][VJS]  Vj[j][b]
    float* cs  = Vj + T * VJS;                           // [T]
    float* red = cs + T;                                 // [THREADS]

    const int tid = threadIdx.x;

    // tile (bi,bj) from linear upper-tri index
    int k = blockIdx.x;
    int bi = 0;
    while (k >= NT - bi) { k -= NT - bi; bi++; }
    const int bj  = bi + k;
    const int gi0 = bi * T;
    const int gj0 = bj * T;
    const bool diag = (bi == bj);

    // ---- stage W tile: transpose + triu mask (1024 float4 loads) ----
    #pragma unroll
    for (int it = 0; it < 2; it++) {
        int idx = it * THREADS + tid;
        int ii  = idx >> 4;
        int q   = idx & 15;
        float4 w = *(const float4*)(W + (size_t)(gi0 + ii) * Nn + gj0 + q * 4);
        int j0 = q * 4;
        if (diag) {
            if (ii > j0 + 0) w.x = 0.0f;
            if (ii > j0 + 1) w.y = 0.0f;
            if (ii > j0 + 2) w.z = 0.0f;
            if (ii > j0 + 3) w.w = 0.0f;
        }
        Wt[(j0 + 0) * WTS + ii] = w.x;
        Wt[(j0 + 1) * WTS + ii] = w.y;
        Wt[(j0 + 2) * WTS + ii] = w.z;
        Wt[(j0 + 3) * WTS + ii] = w.w;
    }

    // ---- stage V slices: Vi packed to u64 [i-pair][b], Vj scalar [j][b] ----
    #pragma unroll
    for (int it = 0; it < 4; it++) {
        int idx = it * THREADS + tid;     // 2048 items
        int b   = idx >> 4;
        int q   = idx & 15;
        float4 a = *(const float4*)(V + (size_t)b * Nn + gi0 + q * 4);
        Vi2[(2 * q + 0) * VI2S + b] = pack2(a.x, a.y);
        Vi2[(2 * q + 1) * VI2S + b] = pack2(a.z, a.w);
        float4 c = *(const float4*)(V + (size_t)b * Nn + gj0 + q * 4);
        Vj[(q * 4 + 0) * VJS + b] = c.x;
        Vj[(q * 4 + 1) * VJS + b] = c.y;
        Vj[(q * 4 + 2) * VJS + b] = c.z;
        Vj[(q * 4 + 3) * VJS + b] = c.w;
    }
    __syncthreads();

    // ---- column sums of masked tile (batch independent) ----
    if (tid < T) {
        float s = 0.0f;
        #pragma unroll
        for (int i = 0; i < T; i++) s += Wt[tid * WTS + i];
        cs[tid] = s;
    }
    __syncthreads();

    // ---- main compute: thread = (batch b, quarter h), 16 j-columns each ----
    const int b = tid & 127;
    const int h = tid >> 7;               // 0..3

    unsigned long long vi2[32];
    #pragma unroll
    for (int p = 0; p < 32; p++) vi2[p] = Vi2[p * VI2S + b];

    float energy = 0.0f;
    for (int jj = 0; jj < 16; jj++) {
        const int j = h * 16 + jj;
        const ulonglong2* wr = (const ulonglong2*)(Wt + j * WTS);
        unsigned long long a0 = 0, a1 = 0, a2 = 0, a3 = 0;
        #pragma unroll
        for (int kk = 0; kk < 16; kk += 2) {
            ulonglong2 w0 = wr[kk];
            ulonglong2 w1 = wr[kk + 1];
            a0 = fma2(w0.x, vi2[2 * kk + 0], a0);
            a1 = fma2(w0.y, vi2[2 * kk + 1], a1);
            a2 = fma2(w1.x, vi2[2 * kk + 2], a2);
            a3 = fma2(w1.y, vi2[2 * kk + 3], a3);
        }
        float x0, x1, x2, x3, x4, x5, x6, x7;
        unpack2(a0, x0, x1); unpack2(a1, x2, x3);
        unpack2(a2, x4, x5); unpack2(a3, x6, x7);
        const float s1 = ((x0 + x1) + (x2 + x3)) + ((x4 + x5) + (x6 + x7));
        const float vbj = Vj[j * VJS + b];
        energy += cs[j] * (1.0f - vbj) + s1 * (2.0f * vbj - 1.0f);
    }

    // ---- CTA reduction over h, then global accumulate ----
    red[tid] = energy;
    __syncthreads();
    if (tid < Bb) {
        float s = red[tid] + red[tid + 128] + red[tid + 256] + red[tid + 384];
        atomicAdd(&g_accum[tid], s);
    }
    __threadfence();
    __syncthreads();

    __shared__ bool last;
    if (tid == 0) last = (atomicAdd(&g_count, 1u) == NTILES - 1);
    __syncthreads();

    if (last) {
        __threadfence();
        if (tid < Bb) out[tid] = atomicExch(&g_accum[tid], 0.0f);  // read + reset
        if (tid == 0) atomicExch(&g_count, 0u);                    // reset for next replay
    }
}

extern "C" void kernel_launch(void* const* d_in, const int* in_sizes, int n_in,
                              void* d_out, int out_size)
{
    const float* V = (const float*)d_in[0];   // vector [128,1024]
    const float* W = (const float*)d_in[1];   // interactions [1024,1024]
    float* out = (float*)d_out;               // [128] fp32

    const int smem_bytes =
        32 * VI2S * 8 +            // Vi2
        (T * WTS + T * VJS + T + THREADS) * (int)sizeof(float);   // 86016
    cudaFuncSetAttribute(potts_fused_k, cudaFuncAttributeMaxDynamicSharedMemorySize,
                         smem_bytes);

    potts_fused_k<<<NTILES, THREADS, smem_bytes>>>(V, W, out);
}